// round 1
// baseline (speedup 1.0000x reference)
#include <cuda_runtime.h>

// ---------------------------------------------------------------------------
// Problem constants (shapes are fixed by the dataset)
// ---------------------------------------------------------------------------
#define NFEAT   128     // node feature dim
#define EFEAT   16      // edge feature dim
#define DDIM    300     // hidden dim
#define DDIM2   600     // 2*D
#define LAYERS  3
#define NGRAPH  256
#define OUTF    128
#define BN_EPS  1e-5f

#define MAX_NODES 50000
#define MAX_EDGES 800000

// ---------------------------------------------------------------------------
// Scratch (device globals; no allocations allowed)
// ---------------------------------------------------------------------------
__device__ float g_hn [MAX_NODES * DDIM];    // node hidden state
__device__ float g_acc[MAX_NODES * DDIM];    // aggregation buffer (init = hn)
__device__ float g_y1 [MAX_NODES * DDIM2];   // pre-BN output of Linear1
__device__ float g_y2 [MAX_NODES * DDIM];    // pre-BN output of Linear2
__device__ float g_sum  [DDIM2];
__device__ float g_sumsq[DDIM2];
__device__ float g_scale[DDIM2];
__device__ float g_shift[DDIM2];
__device__ float g_hg [NGRAPH * DDIM];       // pooled graph embeddings

// ---------------------------------------------------------------------------
// Generic tiled SGEMM: C = f(A) @ B + bias
//   A: [M,K] row-major, optional per-K-column affine transform + relu on load
//   B: [K,N] row-major
//   C (and optional C2): [M,N]
// Tile: BM=128, BN=64, BK=16, 256 threads, 8x4 per-thread microtile.
// ---------------------------------------------------------------------------
#define BM 128
#define BN 64
#define BK 16
#define AS_STRIDE 132   // 128 + 4 pad (keeps float4 alignment, reduces STS conflicts)

__global__ __launch_bounds__(256)
void gemm_kernel(const float* __restrict__ A, const float* __restrict__ B,
                 const float* __restrict__ bias,
                 const float* __restrict__ scaleA, const float* __restrict__ shiftA,
                 int reluA,
                 float* __restrict__ C, float* __restrict__ C2,
                 int M, int N, int K)
{
    __shared__ __align__(16) float As[BK * AS_STRIDE];
    __shared__ __align__(16) float Bs[BK * BN];

    const int tid = threadIdx.x;
    const int tx = tid & 15;        // 0..15  -> N direction (4 cols each)
    const int ty = tid >> 4;        // 0..15  -> M direction (8 rows each)
    const int bm = blockIdx.y * BM;
    const int bn = blockIdx.x * BN;

    float acc[8][4];
#pragma unroll
    for (int i = 0; i < 8; i++)
#pragma unroll
        for (int j = 0; j < 4; j++) acc[i][j] = 0.f;

    for (int kt = 0; kt < K; kt += BK) {
        // ---- load A tile (128 rows x 16 k) transposed into As[k][row] ----
#pragma unroll
        for (int jj = 0; jj < 2; jj++) {
            int loadId = tid + 256 * jj;          // 0..511
            int row = loadId >> 2;                // 0..127
            int q   = loadId & 3;                 // 0..3 (float4 within k)
            int gr  = bm + row;
            int kb  = kt + q * 4;
            float v[4] = {0.f, 0.f, 0.f, 0.f};
            if (gr < M) {
                if (kb + 4 <= K) {
                    float4 t = *(const float4*)(A + (size_t)gr * K + kb);
                    v[0] = t.x; v[1] = t.y; v[2] = t.z; v[3] = t.w;
                } else {
#pragma unroll
                    for (int c = 0; c < 4; c++)
                        if (kb + c < K) v[c] = A[(size_t)gr * K + kb + c];
                }
                if (scaleA) {
#pragma unroll
                    for (int c = 0; c < 4; c++) {
                        if (kb + c < K) {
                            float t = fmaf(v[c], scaleA[kb + c], shiftA[kb + c]);
                            v[c] = reluA ? fmaxf(t, 0.f) : t;
                        }
                    }
                }
            }
#pragma unroll
            for (int c = 0; c < 4; c++)
                As[(q * 4 + c) * AS_STRIDE + row] = v[c];
        }
        // ---- load B tile (16 k x 64 cols) into Bs[k][n] ----
        {
            int k  = tid >> 4;                    // 0..15
            int n0 = (tid & 15) * 4;
            int gk = kt + k;
            int gn = bn + n0;
            float v[4] = {0.f, 0.f, 0.f, 0.f};
            if (gk < K) {
                if (gn + 4 <= N) {
                    float4 t = *(const float4*)(B + (size_t)gk * N + gn);
                    v[0] = t.x; v[1] = t.y; v[2] = t.z; v[3] = t.w;
                } else {
#pragma unroll
                    for (int c = 0; c < 4; c++)
                        if (gn + c < N) v[c] = B[(size_t)gk * N + gn + c];
                }
            }
            *(float4*)&Bs[k * BN + n0] = make_float4(v[0], v[1], v[2], v[3]);
        }
        __syncthreads();

        // ---- compute ----
#pragma unroll
        for (int k = 0; k < BK; k++) {
            float4 a0 = *(const float4*)&As[k * AS_STRIDE + ty * 8];
            float4 a1 = *(const float4*)&As[k * AS_STRIDE + ty * 8 + 4];
            float4 b0 = *(const float4*)&Bs[k * BN + tx * 4];
            float av[8] = {a0.x, a0.y, a0.z, a0.w, a1.x, a1.y, a1.z, a1.w};
            float bv[4] = {b0.x, b0.y, b0.z, b0.w};
#pragma unroll
            for (int i = 0; i < 8; i++)
#pragma unroll
                for (int j = 0; j < 4; j++)
                    acc[i][j] = fmaf(av[i], bv[j], acc[i][j]);
        }
        __syncthreads();
    }

    // ---- epilogue: bias, store (optionally to two buffers) ----
#pragma unroll
    for (int i = 0; i < 8; i++) {
        int row = bm + ty * 8 + i;
        if (row >= M) continue;
        int col = bn + tx * 4;
        if (col + 4 <= N) {
            float4 o;
            o.x = acc[i][0] + bias[col + 0];
            o.y = acc[i][1] + bias[col + 1];
            o.z = acc[i][2] + bias[col + 2];
            o.w = acc[i][3] + bias[col + 3];
            *(float4*)(C + (size_t)row * N + col) = o;
            if (C2) *(float4*)(C2 + (size_t)row * N + col) = o;
        } else {
#pragma unroll
            for (int j = 0; j < 4; j++) {
                if (col + j < N) {
                    float o = acc[i][j] + bias[col + j];
                    C[(size_t)row * N + col + j] = o;
                    if (C2) C2[(size_t)row * N + col + j] = o;
                }
            }
        }
    }
}

// ---------------------------------------------------------------------------
// Edge encoder + message + scatter:
//   for each edge e: he = edge_feat[e] @ eW + eb   (K=16)
//                    msg = relu(hn[src[e]] + he)
//                    acc[dst[e]] += msg            (vectorized red.v4)
// One warp per edge; edge_W kept in smem.
// ---------------------------------------------------------------------------
#define EPB 128                 // edges per block (8 warps x 16 edges)

__global__ __launch_bounds__(256)
void scatter_kernel(const float* __restrict__ edge_feat,
                    const int* __restrict__ src, const int* __restrict__ dst,
                    const float* __restrict__ eW, const float* __restrict__ eb,
                    const float* __restrict__ hn, float* __restrict__ acc, int E)
{
    __shared__ __align__(16) float Ws[EFEAT * DDIM];  // 4800 floats
    __shared__ __align__(16) float bs[DDIM];

    const int tid = threadIdx.x;
    for (int i = tid; i < EFEAT * DDIM; i += 256) Ws[i] = eW[i];
    for (int i = tid; i < DDIM; i += 256) bs[i] = eb[i];
    __syncthreads();

    const int warp = tid >> 5;
    const int lane = tid & 31;
    const int e0 = blockIdx.x * EPB + warp * (EPB / 8);
    const int e1 = min(e0 + (EPB / 8), E);

    for (int e = e0; e < e1; e++) {
        const int se = src[e];
        const int de = dst[e];
        const float4* ef4 = (const float4*)(edge_feat + (size_t)e * EFEAT);
        float efv[16];
#pragma unroll
        for (int i = 0; i < 4; i++) {
            float4 t = ef4[i];
            efv[4*i+0] = t.x; efv[4*i+1] = t.y; efv[4*i+2] = t.z; efv[4*i+3] = t.w;
        }
        const float* hrow = hn  + (size_t)se * DDIM;
        float*       arow = acc + (size_t)de * DDIM;

        for (int q = lane; q < DDIM / 4; q += 32) {
            const int d0 = q * 4;
            float4 h = *(const float4*)(bs + d0);
#pragma unroll
            for (int k = 0; k < 16; k++) {
                float ev = efv[k];
                float4 w = *(const float4*)(Ws + k * DDIM + d0);
                h.x = fmaf(ev, w.x, h.x);
                h.y = fmaf(ev, w.y, h.y);
                h.z = fmaf(ev, w.z, h.z);
                h.w = fmaf(ev, w.w, h.w);
            }
            float4 s = *(const float4*)(hrow + d0);
            float mx = fmaxf(s.x + h.x, 0.f);
            float my = fmaxf(s.y + h.y, 0.f);
            float mz = fmaxf(s.z + h.z, 0.f);
            float mw = fmaxf(s.w + h.w, 0.f);
            asm volatile("red.global.add.v4.f32 [%0], {%1,%2,%3,%4};"
                         :: "l"(arow + d0), "f"(mx), "f"(my), "f"(mz), "f"(mw)
                         : "memory");
        }
    }
}

// ---------------------------------------------------------------------------
// BatchNorm statistics: per-column sum & sumsq (block partials + atomics)
// ---------------------------------------------------------------------------
__global__ void zero_stats_kernel()
{
    int i = threadIdx.x + blockIdx.x * blockDim.x;
    if (i < DDIM2) { g_sum[i] = 0.f; g_sumsq[i] = 0.f; }
}

__global__ void colstats_kernel(const float* __restrict__ Y, int M, int Nc, int rowsPer)
{
    int c = threadIdx.x;
    if (c >= Nc) return;
    int r0 = blockIdx.x * rowsPer;
    int r1 = min(r0 + rowsPer, M);
    float s = 0.f, ss = 0.f;
    for (int r = r0; r < r1; r++) {
        float v = Y[(size_t)r * Nc + c];
        s += v;
        ss = fmaf(v, v, ss);
    }
    atomicAdd(&g_sum[c], s);
    atomicAdd(&g_sumsq[c], ss);
}

__global__ void finalize_kernel(const float* __restrict__ gamma,
                                const float* __restrict__ beta, int Nc, int M)
{
    int c = threadIdx.x + blockIdx.x * blockDim.x;
    if (c >= Nc) return;
    float invM = 1.f / (float)M;
    float mean = g_sum[c] * invM;
    float var  = fmaxf(g_sumsq[c] * invM - mean * mean, 0.f);
    float sc   = gamma[c] * rsqrtf(var + BN_EPS);
    g_scale[c] = sc;
    g_shift[c] = beta[c] - mean * sc;
}

// Apply BN2 (+ optional relu); write hn and (if accOut) re-seed acc = hn.
__global__ void apply_bn_kernel(const float* __restrict__ Y,
                                float* __restrict__ hn, float* __restrict__ accOut,
                                int relu, int total4)
{
    int i4 = threadIdx.x + blockIdx.x * blockDim.x;
    if (i4 >= total4) return;
    size_t idx = (size_t)i4 * 4;
    int d0 = (int)(idx % DDIM);                 // DDIM % 4 == 0, no row crossing
    float4 v = *(const float4*)(Y + idx);
    float4 o;
    o.x = fmaf(v.x, g_scale[d0+0], g_shift[d0+0]);
    o.y = fmaf(v.y, g_scale[d0+1], g_shift[d0+1]);
    o.z = fmaf(v.z, g_scale[d0+2], g_shift[d0+2]);
    o.w = fmaf(v.w, g_scale[d0+3], g_shift[d0+3]);
    if (relu) {
        o.x = fmaxf(o.x, 0.f); o.y = fmaxf(o.y, 0.f);
        o.z = fmaxf(o.z, 0.f); o.w = fmaxf(o.w, 0.f);
    }
    *(float4*)(hn + idx) = o;
    if (accOut) *(float4*)(accOut + idx) = o;
}

// ---------------------------------------------------------------------------
// Mean pooling: one block per graph, boundaries via binary search (gid sorted)
// ---------------------------------------------------------------------------
__device__ __forceinline__ int lower_bound_dev(const int* a, int n, int key)
{
    int lo = 0, hi = n;
    while (lo < hi) {
        int mid = (lo + hi) >> 1;
        if (a[mid] < key) lo = mid + 1; else hi = mid;
    }
    return lo;
}

__global__ void pool_kernel(const float* __restrict__ hn,
                            const int* __restrict__ gid, int Nn)
{
    __shared__ int s_lo, s_hi;
    int g = blockIdx.x;
    if (threadIdx.x == 0) {
        s_lo = lower_bound_dev(gid, Nn, g);
        s_hi = lower_bound_dev(gid, Nn, g + 1);
    }
    __syncthreads();
    int lo = s_lo, hi = s_hi;
    float inv = 1.f / fmaxf((float)(hi - lo), 1.f);
    for (int d = threadIdx.x; d < DDIM; d += blockDim.x) {
        float s = 0.f;
        for (int r = lo; r < hi; r++) s += hn[(size_t)r * DDIM + d];
        g_hg[g * DDIM + d] = s * inv;
    }
}

// Prediction head: out[g,o] = hg[g] . pred_W[:,o] + pred_b[o]
__global__ void pred_kernel(const float* __restrict__ W,
                            const float* __restrict__ b, float* __restrict__ out)
{
    __shared__ float h[DDIM];
    int g = blockIdx.x;
    for (int i = threadIdx.x; i < DDIM; i += blockDim.x) h[i] = g_hg[g * DDIM + i];
    __syncthreads();
    int o = threadIdx.x;          // 128 threads
    float s = b[o];
    for (int k = 0; k < DDIM; k++)
        s = fmaf(h[k], W[k * OUTF + o], s);
    out[g * OUTF + o] = s;
}

// ---------------------------------------------------------------------------
// Launch
// ---------------------------------------------------------------------------
static inline int ceil_div(int a, int b) { return (a + b - 1) / b; }

extern "C" void kernel_launch(void* const* d_in, const int* in_sizes, int n_in,
                              void* d_out, int out_size)
{
    const float* node_feat = (const float*)d_in[0];
    const float* edge_feat = (const float*)d_in[1];
    const int*   src       = (const int*)d_in[2];
    const int*   dst       = (const int*)d_in[3];
    const int*   gid       = (const int*)d_in[4];

    // num_graphs may (or may not) appear as a 1-element scalar input at slot 5
    int base = 5;
    if (in_sizes[5] == 1) base = 6;

    const float* node_W = (const float*)d_in[base + 0];
    const float* node_b = (const float*)d_in[base + 1];
    const float* edge_W = (const float*)d_in[base + 2];   // [L,16,300]
    const float* edge_b = (const float*)d_in[base + 3];   // [L,300]
    const float* W1     = (const float*)d_in[base + 4];   // [L,300,600]
    const float* b1     = (const float*)d_in[base + 5];
    const float* g1     = (const float*)d_in[base + 6];
    const float* beta1  = (const float*)d_in[base + 7];
    const float* W2     = (const float*)d_in[base + 8];   // [L,600,300]
    const float* b2     = (const float*)d_in[base + 9];
    const float* g2     = (const float*)d_in[base + 10];
    const float* beta2  = (const float*)d_in[base + 11];
    const float* pred_W = (const float*)d_in[base + 12];
    const float* pred_b = (const float*)d_in[base + 13];

    const int Nn = in_sizes[0] / NFEAT;
    const int E  = in_sizes[1] / EFEAT;

    float *hn, *acc, *y1, *y2;
    cudaGetSymbolAddress((void**)&hn,  g_hn);
    cudaGetSymbolAddress((void**)&acc, g_acc);
    cudaGetSymbolAddress((void**)&y1,  g_y1);
    cudaGetSymbolAddress((void**)&y2,  g_y2);

    // ---- node encoder: hn = node_feat @ node_W + node_b ; acc = hn ----
    {
        dim3 grid(ceil_div(DDIM, BN), ceil_div(Nn, BM));
        gemm_kernel<<<grid, 256>>>(node_feat, node_W, node_b,
                                   nullptr, nullptr, 0,
                                   hn, acc, Nn, DDIM, NFEAT);
    }

    const int statRows = 196;
    const int statGrid = ceil_div(Nn, statRows);

    for (int l = 0; l < LAYERS; l++) {
        // ---- edge encode + message + aggregate into acc ----
        scatter_kernel<<<ceil_div(E, EPB), 256>>>(
            edge_feat, src, dst,
            edge_W + (size_t)l * EFEAT * DDIM, edge_b + (size_t)l * DDIM,
            hn, acc, E);

        // ---- Linear1: y1 = acc @ W1[l] + b1[l] ----
        {
            dim3 grid(ceil_div(DDIM2, BN), ceil_div(Nn, BM));
            gemm_kernel<<<grid, 256>>>(acc, W1 + (size_t)l * DDIM * DDIM2,
                                       b1 + (size_t)l * DDIM2,
                                       nullptr, nullptr, 0,
                                       y1, nullptr, Nn, DDIM2, DDIM);
        }
        // ---- BN1 stats ----
        zero_stats_kernel<<<1, DDIM2>>>();
        colstats_kernel<<<statGrid, 640>>>(y1, Nn, DDIM2, statRows);
        finalize_kernel<<<1, DDIM2>>>(g1 + (size_t)l * DDIM2,
                                      beta1 + (size_t)l * DDIM2, DDIM2, Nn);

        // ---- Linear2 with fused BN1+ReLU on input: y2 = relu(bn(y1)) @ W2 + b2 ----
        {
            float *scl, *shf;
            cudaGetSymbolAddress((void**)&scl, g_scale);
            cudaGetSymbolAddress((void**)&shf, g_shift);
            dim3 grid(ceil_div(DDIM, BN), ceil_div(Nn, BM));
            gemm_kernel<<<grid, 256>>>(y1, W2 + (size_t)l * DDIM2 * DDIM,
                                       b2 + (size_t)l * DDIM,
                                       scl, shf, 1,
                                       y2, nullptr, Nn, DDIM, DDIM2);
        }
        // ---- BN2 stats ----
        zero_stats_kernel<<<1, DDIM2>>>();
        colstats_kernel<<<statGrid, 320>>>(y2, Nn, DDIM, statRows);
        finalize_kernel<<<1, DDIM>>>(g2 + (size_t)l * DDIM,
                                     beta2 + (size_t)l * DDIM, DDIM, Nn);

        // ---- apply BN2 (+relu except last layer); re-seed acc for next layer ----
        {
            int total4 = Nn * DDIM / 4;
            int relu = (l != LAYERS - 1) ? 1 : 0;
            float* accOut = (l != LAYERS - 1) ? acc : nullptr;
            apply_bn_kernel<<<ceil_div(total4, 256), 256>>>(y2, hn, accOut,
                                                            relu, total4);
        }
    }

    // ---- mean pool + prediction head ----
    pool_kernel<<<NGRAPH, 256>>>(hn, gid, Nn);
    pred_kernel<<<NGRAPH, OUTF>>>(pred_W, pred_b, (float*)d_out);
}

// round 4
// speedup vs baseline: 1.1142x; 1.1142x over previous
#include <cuda_runtime.h>
#include <cstdint>

// ---------------------------------------------------------------------------
// Problem constants
// ---------------------------------------------------------------------------
#define NFEAT   128
#define EFEAT   16
#define DDIM    300
#define DDIM2   600
#define LAYERS  3
#define NGRAPH  256
#define OUTF    128
#define BN_EPS  1e-5f

#define MAX_NODES 50000
#define MAX_EDGES 800000

// ---------------------------------------------------------------------------
// Scratch (device globals; no allocations allowed)
// ---------------------------------------------------------------------------
__device__ float g_hn [MAX_NODES * DDIM];
__device__ float g_acc[MAX_NODES * DDIM];
__device__ float g_y1 [MAX_NODES * DDIM2];
__device__ float g_y2 [MAX_NODES * DDIM];
__device__ float g_sum  [DDIM2];
__device__ float g_sumsq[DDIM2];
__device__ float g_scale[DDIM2];
__device__ float g_shift[DDIM2];
__device__ float g_hg [NGRAPH * DDIM];

// ---------------------------------------------------------------------------
// Split-TF32 (3xTF32) tensor-core GEMM:  C = f(A) @ B + bias
// Each fp32 operand is split hi/lo in tf32; acc += lo*hi + hi*lo + hi*hi
// gives ~21 mantissa bits (fp32-class accuracy) at 3 MMAs per pair.
// Block tile 128x64x32, 8 warps (4x2), warp tile 32x32 via m16n8k8.
// Smem holds raw fp32; layouts padded for conflict-free fragment LDS.
// ---------------------------------------------------------------------------
#define TBM 128
#define TBN 64
#define TBK 32
#define AS_STR 36
#define BS_STR 72

__device__ __forceinline__ void split_tf32(float x, uint32_t& hi, uint32_t& lo)
{
    uint32_t h;
    asm("cvt.rna.tf32.f32 %0, %1;" : "=r"(h) : "f"(x));
    float rem = x - __uint_as_float(h);
    uint32_t l;
    asm("cvt.rna.tf32.f32 %0, %1;" : "=r"(l) : "f"(rem));
    hi = h; lo = l;
}

__device__ __forceinline__ void mma_tf32(float acc[4], const uint32_t a[4],
                                         const uint32_t b[2])
{
    asm volatile(
        "mma.sync.aligned.m16n8k8.row.col.f32.tf32.tf32.f32 "
        "{%0,%1,%2,%3}, {%4,%5,%6,%7}, {%8,%9}, {%0,%1,%2,%3};"
        : "+f"(acc[0]), "+f"(acc[1]), "+f"(acc[2]), "+f"(acc[3])
        : "r"(a[0]), "r"(a[1]), "r"(a[2]), "r"(a[3]), "r"(b[0]), "r"(b[1]));
}

__global__ __launch_bounds__(256)
void gemm_tf32_kernel(const float* __restrict__ A, const float* __restrict__ B,
                      const float* __restrict__ bias,
                      const float* __restrict__ scaleA,
                      const float* __restrict__ shiftA, int reluA,
                      float* __restrict__ C, float* __restrict__ C2,
                      int M, int N, int K)
{
    __shared__ __align__(16) float As[TBM * AS_STR];
    __shared__ __align__(16) float Bs[TBK * BS_STR];

    const int tid  = threadIdx.x;
    const int warp = tid >> 5;
    const int lane = tid & 31;
    const int wm = warp >> 1;        // 0..3
    const int wn = warp & 1;         // 0..1
    const int r  = lane >> 2;        // 0..7
    const int c  = lane & 3;         // 0..3
    const int bm = blockIdx.y * TBM;
    const int bn = blockIdx.x * TBN;

    float acc[2][4][4];
#pragma unroll
    for (int mt = 0; mt < 2; mt++)
#pragma unroll
        for (int nt = 0; nt < 4; nt++)
#pragma unroll
            for (int i = 0; i < 4; i++) acc[mt][nt][i] = 0.f;

    for (int kt = 0; kt < K; kt += TBK) {
        // ---- A tile: 128 rows x 32 k (raw fp32, BN/relu fused on load) ----
#pragma unroll
        for (int j = 0; j < 4; j++) {
            int v   = tid + 256 * j;       // 0..1023
            int row = v >> 3;              // 0..127
            int kq  = v & 7;               // float4 index in k
            int gr  = bm + row;
            int gk  = kt + kq * 4;
            float t[4] = {0.f, 0.f, 0.f, 0.f};
            if (gr < M && gk < K) {
                if (gk + 4 <= K) {
                    float4 q = *(const float4*)(A + (size_t)gr * K + gk);
                    t[0] = q.x; t[1] = q.y; t[2] = q.z; t[3] = q.w;
                } else {
#pragma unroll
                    for (int i = 0; i < 4; i++)
                        if (gk + i < K) t[i] = A[(size_t)gr * K + gk + i];
                }
                if (scaleA) {
#pragma unroll
                    for (int i = 0; i < 4; i++) {
                        if (gk + i < K) {
                            float u = fmaf(t[i], scaleA[gk + i], shiftA[gk + i]);
                            t[i] = reluA ? fmaxf(u, 0.f) : u;
                        }
                    }
                }
            }
#pragma unroll
            for (int i = 0; i < 4; i++)
                As[row * AS_STR + kq * 4 + i] = t[i];
        }
        // ---- B tile: 32 k x 64 n (raw fp32) ----
#pragma unroll
        for (int j = 0; j < 2; j++) {
            int v  = tid + 256 * j;        // 0..511
            int k  = v >> 4;               // 0..31
            int nq = v & 15;
            int gk = kt + k;
            int gn = bn + nq * 4;
            float t[4] = {0.f, 0.f, 0.f, 0.f};
            if (gk < K && gn < N) {        // N % 4 == 0 for all shapes here
                float4 q = *(const float4*)(B + (size_t)gk * N + gn);
                t[0] = q.x; t[1] = q.y; t[2] = q.z; t[3] = q.w;
            }
#pragma unroll
            for (int i = 0; i < 4; i++)
                Bs[k * BS_STR + nq * 4 + i] = t[i];
        }
        __syncthreads();

        // ---- 4 k-steps of split m16n8k8 ----
#pragma unroll
        for (int ks = 0; ks < 4; ks++) {
            uint32_t ah[2][4], al[2][4];
#pragma unroll
            for (int mt = 0; mt < 2; mt++) {
                int m0 = wm * 32 + mt * 16;
                const float* ap = As + (size_t)(m0 + r) * AS_STR + ks * 8 + c;
                split_tf32(ap[0],              ah[mt][0], al[mt][0]);
                split_tf32(ap[8 * AS_STR],     ah[mt][1], al[mt][1]);
                split_tf32(ap[4],              ah[mt][2], al[mt][2]);
                split_tf32(ap[8 * AS_STR + 4], ah[mt][3], al[mt][3]);
            }
            uint32_t bh[4][2], bl[4][2];
#pragma unroll
            for (int nt = 0; nt < 4; nt++) {
                int n0 = wn * 32 + nt * 8;
                const float* bp = Bs + (size_t)(ks * 8 + c) * BS_STR + n0 + r;
                split_tf32(bp[0],          bh[nt][0], bl[nt][0]);
                split_tf32(bp[4 * BS_STR], bh[nt][1], bl[nt][1]);
            }
#pragma unroll
            for (int mt = 0; mt < 2; mt++)
#pragma unroll
                for (int nt = 0; nt < 4; nt++) {
                    mma_tf32(acc[mt][nt], al[mt], bh[nt]);
                    mma_tf32(acc[mt][nt], ah[mt], bl[nt]);
                    mma_tf32(acc[mt][nt], ah[mt], bh[nt]);
                }
        }
        __syncthreads();
    }

    // ---- epilogue ----
#pragma unroll
    for (int mt = 0; mt < 2; mt++) {
        int row0 = bm + wm * 32 + mt * 16 + r;
#pragma unroll
        for (int nt = 0; nt < 4; nt++) {
            int col = bn + wn * 32 + nt * 8 + 2 * c;
            if (col >= N) continue;             // N even -> col+1 < N too
            float bx = bias[col], by = bias[col + 1];
            if (row0 < M) {
                float2 o = make_float2(acc[mt][nt][0] + bx, acc[mt][nt][1] + by);
                *(float2*)(C + (size_t)row0 * N + col) = o;
                if (C2) *(float2*)(C2 + (size_t)row0 * N + col) = o;
            }
            int row1 = row0 + 8;
            if (row1 < M) {
                float2 o = make_float2(acc[mt][nt][2] + bx, acc[mt][nt][3] + by);
                *(float2*)(C + (size_t)row1 * N + col) = o;
                if (C2) *(float2*)(C2 + (size_t)row1 * N + col) = o;
            }
        }
    }
}

// ---------------------------------------------------------------------------
// Edge encoder + message + scatter
// ---------------------------------------------------------------------------
#define EPB 128

__global__ __launch_bounds__(256)
void scatter_kernel(const float* __restrict__ edge_feat,
                    const int* __restrict__ src, const int* __restrict__ dst,
                    const float* __restrict__ eW, const float* __restrict__ eb,
                    const float* __restrict__ hn, float* __restrict__ acc, int E)
{
    __shared__ __align__(16) float Ws[EFEAT * DDIM];
    __shared__ __align__(16) float bs[DDIM];

    const int tid = threadIdx.x;
    for (int i = tid; i < EFEAT * DDIM; i += 256) Ws[i] = eW[i];
    for (int i = tid; i < DDIM; i += 256) bs[i] = eb[i];
    __syncthreads();

    const int warp = tid >> 5;
    const int lane = tid & 31;
    const int e0 = blockIdx.x * EPB + warp * (EPB / 8);
    const int e1 = min(e0 + (EPB / 8), E);

    for (int e = e0; e < e1; e++) {
        const int se = src[e];
        const int de = dst[e];
        const float4* ef4 = (const float4*)(edge_feat + (size_t)e * EFEAT);
        float efv[16];
#pragma unroll
        for (int i = 0; i < 4; i++) {
            float4 t = ef4[i];
            efv[4*i+0] = t.x; efv[4*i+1] = t.y; efv[4*i+2] = t.z; efv[4*i+3] = t.w;
        }
        const float* hrow = hn  + (size_t)se * DDIM;
        float*       arow = acc + (size_t)de * DDIM;

        for (int q = lane; q < DDIM / 4; q += 32) {
            const int d0 = q * 4;
            float4 h = *(const float4*)(bs + d0);
#pragma unroll
            for (int k = 0; k < 16; k++) {
                float ev = efv[k];
                float4 w = *(const float4*)(Ws + k * DDIM + d0);
                h.x = fmaf(ev, w.x, h.x);
                h.y = fmaf(ev, w.y, h.y);
                h.z = fmaf(ev, w.z, h.z);
                h.w = fmaf(ev, w.w, h.w);
            }
            float4 s = *(const float4*)(hrow + d0);
            float mx = fmaxf(s.x + h.x, 0.f);
            float my = fmaxf(s.y + h.y, 0.f);
            float mz = fmaxf(s.z + h.z, 0.f);
            float mw = fmaxf(s.w + h.w, 0.f);
            asm volatile("red.global.add.v4.f32 [%0], {%1,%2,%3,%4};"
                         :: "l"(arow + d0), "f"(mx), "f"(my), "f"(mz), "f"(mw)
                         : "memory");
        }
    }
}

// ---------------------------------------------------------------------------
// BatchNorm statistics
// ---------------------------------------------------------------------------
__global__ void zero_stats_kernel()
{
    int i = threadIdx.x + blockIdx.x * blockDim.x;
    if (i < DDIM2) { g_sum[i] = 0.f; g_sumsq[i] = 0.f; }
}

__global__ void colstats_kernel(const float* __restrict__ Y, int M, int Nc, int rowsPer)
{
    int c = threadIdx.x;
    if (c >= Nc) return;
    int r0 = blockIdx.x * rowsPer;
    int r1 = min(r0 + rowsPer, M);
    float s = 0.f, ss = 0.f;
    for (int r = r0; r < r1; r++) {
        float v = Y[(size_t)r * Nc + c];
        s += v;
        ss = fmaf(v, v, ss);
    }
    atomicAdd(&g_sum[c], s);
    atomicAdd(&g_sumsq[c], ss);
}

__global__ void finalize_kernel(const float* __restrict__ gamma,
                                const float* __restrict__ beta, int Nc, int M)
{
    int c = threadIdx.x + blockIdx.x * blockDim.x;
    if (c >= Nc) return;
    float invM = 1.f / (float)M;
    float mean = g_sum[c] * invM;
    float var  = fmaxf(g_sumsq[c] * invM - mean * mean, 0.f);
    float sc   = gamma[c] * rsqrtf(var + BN_EPS);
    g_scale[c] = sc;
    g_shift[c] = beta[c] - mean * sc;
}

__global__ void apply_bn_kernel(const float* __restrict__ Y,
                                float* __restrict__ hn, float* __restrict__ accOut,
                                int relu, int total4)
{
    int i4 = threadIdx.x + blockIdx.x * blockDim.x;
    if (i4 >= total4) return;
    size_t idx = (size_t)i4 * 4;
    int d0 = (int)(idx % DDIM);
    float4 v = *(const float4*)(Y + idx);
    float4 o;
    o.x = fmaf(v.x, g_scale[d0+0], g_shift[d0+0]);
    o.y = fmaf(v.y, g_scale[d0+1], g_shift[d0+1]);
    o.z = fmaf(v.z, g_scale[d0+2], g_shift[d0+2]);
    o.w = fmaf(v.w, g_scale[d0+3], g_shift[d0+3]);
    if (relu) {
        o.x = fmaxf(o.x, 0.f); o.y = fmaxf(o.y, 0.f);
        o.z = fmaxf(o.z, 0.f); o.w = fmaxf(o.w, 0.f);
    }
    *(float4*)(hn + idx) = o;
    if (accOut) *(float4*)(accOut + idx) = o;
}

// ---------------------------------------------------------------------------
// Mean pooling + head
// ---------------------------------------------------------------------------
__device__ __forceinline__ int lower_bound_dev(const int* a, int n, int key)
{
    int lo = 0, hi = n;
    while (lo < hi) {
        int mid = (lo + hi) >> 1;
        if (a[mid] < key) lo = mid + 1; else hi = mid;
    }
    return lo;
}

__global__ void pool_kernel(const float* __restrict__ hn,
                            const int* __restrict__ gid, int Nn)
{
    __shared__ int s_lo, s_hi;
    int g = blockIdx.x;
    if (threadIdx.x == 0) {
        s_lo = lower_bound_dev(gid, Nn, g);
        s_hi = lower_bound_dev(gid, Nn, g + 1);
    }
    __syncthreads();
    int lo = s_lo, hi = s_hi;
    float inv = 1.f / fmaxf((float)(hi - lo), 1.f);
    for (int d = threadIdx.x; d < DDIM; d += blockDim.x) {
        float s = 0.f;
        for (int r = lo; r < hi; r++) s += hn[(size_t)r * DDIM + d];
        g_hg[g * DDIM + d] = s * inv;
    }
}

__global__ void pred_kernel(const float* __restrict__ W,
                            const float* __restrict__ b, float* __restrict__ out)
{
    __shared__ float h[DDIM];
    int g = blockIdx.x;
    for (int i = threadIdx.x; i < DDIM; i += blockDim.x) h[i] = g_hg[g * DDIM + i];
    __syncthreads();
    int o = threadIdx.x;
    float s = b[o];
    for (int k = 0; k < DDIM; k++)
        s = fmaf(h[k], W[k * OUTF + o], s);
    out[g * OUTF + o] = s;
}

// ---------------------------------------------------------------------------
// Launch
// ---------------------------------------------------------------------------
static inline int ceil_div(int a, int b) { return (a + b - 1) / b; }

extern "C" void kernel_launch(void* const* d_in, const int* in_sizes, int n_in,
                              void* d_out, int out_size)
{
    const float* node_feat = (const float*)d_in[0];
    const float* edge_feat = (const float*)d_in[1];
    const int*   src       = (const int*)d_in[2];
    const int*   dst       = (const int*)d_in[3];
    const int*   gid       = (const int*)d_in[4];

    int base = 5;
    if (in_sizes[5] == 1) base = 6;

    const float* node_W = (const float*)d_in[base + 0];
    const float* node_b = (const float*)d_in[base + 1];
    const float* edge_W = (const float*)d_in[base + 2];
    const float* edge_b = (const float*)d_in[base + 3];
    const float* W1     = (const float*)d_in[base + 4];
    const float* b1     = (const float*)d_in[base + 5];
    const float* g1     = (const float*)d_in[base + 6];
    const float* beta1  = (const float*)d_in[base + 7];
    const float* W2     = (const float*)d_in[base + 8];
    const float* b2     = (const float*)d_in[base + 9];
    const float* g2     = (const float*)d_in[base + 10];
    const float* beta2  = (const float*)d_in[base + 11];
    const float* pred_W = (const float*)d_in[base + 12];
    const float* pred_b = (const float*)d_in[base + 13];

    const int Nn = in_sizes[0] / NFEAT;
    const int E  = in_sizes[1] / EFEAT;

    float *hn, *acc, *y1, *y2, *scl, *shf;
    cudaGetSymbolAddress((void**)&hn,  g_hn);
    cudaGetSymbolAddress((void**)&acc, g_acc);
    cudaGetSymbolAddress((void**)&y1,  g_y1);
    cudaGetSymbolAddress((void**)&y2,  g_y2);
    cudaGetSymbolAddress((void**)&scl, g_scale);
    cudaGetSymbolAddress((void**)&shf, g_shift);

    // ---- node encoder ----
    {
        dim3 grid(ceil_div(DDIM, TBN), ceil_div(Nn, TBM));
        gemm_tf32_kernel<<<grid, 256>>>(node_feat, node_W, node_b,
                                        nullptr, nullptr, 0,
                                        hn, acc, Nn, DDIM, NFEAT);
    }

    const int statRows = 196;
    const int statGrid = ceil_div(Nn, statRows);

    for (int l = 0; l < LAYERS; l++) {
        scatter_kernel<<<ceil_div(E, EPB), 256>>>(
            edge_feat, src, dst,
            edge_W + (size_t)l * EFEAT * DDIM, edge_b + (size_t)l * DDIM,
            hn, acc, E);

        // Linear1
        {
            dim3 grid(ceil_div(DDIM2, TBN), ceil_div(Nn, TBM));
            gemm_tf32_kernel<<<grid, 256>>>(acc, W1 + (size_t)l * DDIM * DDIM2,
                                            b1 + (size_t)l * DDIM2,
                                            nullptr, nullptr, 0,
                                            y1, nullptr, Nn, DDIM2, DDIM);
        }
        zero_stats_kernel<<<1, DDIM2>>>();
        colstats_kernel<<<statGrid, 640>>>(y1, Nn, DDIM2, statRows);
        finalize_kernel<<<1, DDIM2>>>(g1 + (size_t)l * DDIM2,
                                      beta1 + (size_t)l * DDIM2, DDIM2, Nn);

        // Linear2 with fused BN1 + relu on A
        {
            dim3 grid(ceil_div(DDIM, TBN), ceil_div(Nn, TBM));
            gemm_tf32_kernel<<<grid, 256>>>(y1, W2 + (size_t)l * DDIM2 * DDIM,
                                            b2 + (size_t)l * DDIM,
                                            scl, shf, 1,
                                            y2, nullptr, Nn, DDIM, DDIM2);
        }
        zero_stats_kernel<<<1, DDIM2>>>();
        colstats_kernel<<<statGrid, 320>>>(y2, Nn, DDIM, statRows);
        finalize_kernel<<<1, DDIM>>>(g2 + (size_t)l * DDIM,
                                     beta2 + (size_t)l * DDIM, DDIM, Nn);

        {
            int total4 = Nn * DDIM / 4;
            int relu = (l != LAYERS - 1) ? 1 : 0;
            float* accOut = (l != LAYERS - 1) ? acc : nullptr;
            apply_bn_kernel<<<ceil_div(total4, 256), 256>>>(y2, hn, accOut,
                                                            relu, total4);
        }
    }

    pool_kernel<<<NGRAPH, 256>>>(hn, gid, Nn);
    pred_kernel<<<NGRAPH, OUTF>>>(pred_W, pred_b, (float*)d_out);
}